// round 12
// baseline (speedup 1.0000x reference)
#include <cuda_runtime.h>
#include <cuda_bf16.h>
#include <cstdint>

// ---------------- problem constants ----------------
static constexpr int NROWS   = 8192;
static constexpr int DDIM    = 1024;
static constexpr float MARGIN = 0.3f;

// Tile enumeration in units of 128x256 tiles over the lower triangle:
// row-tile bi (of 64, 128 rows each) needs col-tiles 0..bi/2 -> 1056 total.
// First 1036 = 7 x 148 run as full tiles (7 exact waves);
// last 20 run split into 40 half-tiles (128x128) in one cheap wave.
static constexpr int NT_FULL  = 1036;
static constexpr int NT_SPLIT = 20;
static constexpr int NPARTS   = NT_FULL + 2 * NT_SPLIT;   // 1076 partials

static constexpr int STAGES   = 3;
static constexpr int BK       = 64;                 // bf16 per K chunk (128 B/row)
static constexpr int NKCHUNKS = DDIM / BK;          // 16
static constexpr int NTHREADS = 512;                // 16 warps -> 4 per SMSP

// ---------------- scratch (no allocs allowed) ----------------
__device__ __nv_bfloat16 g_xb[(size_t)NROWS * DDIM];  // 16MB bf16 copy of X
__device__ int   g_tgt[NROWS];
__device__ float g_partials[NPARTS];

// ---------------- helpers ----------------
__device__ __forceinline__ uint32_t smem_to_u32(const void* p) {
    uint32_t a;
    asm("{ .reg .u64 t; cvta.to.shared.u64 t, %1; cvt.u32.u64 %0, t; }" : "=r"(a) : "l"(p));
    return a;
}
#define SW128(off) ((off) ^ (((off) >> 3) & 0x70))

__device__ __forceinline__ void cp_async16(uint32_t smem_dst, const void* gptr) {
    asm volatile("cp.async.cg.shared.global [%0], [%1], 16;"
        :: "r"(smem_dst), "l"(__cvta_generic_to_global(gptr)) : "memory");
}
__device__ __forceinline__ void cp_commit() {
    asm volatile("cp.async.commit_group;" ::: "memory");
}
template <int N> __device__ __forceinline__ void cp_wait() {
    asm volatile("cp.async.wait_group %0;" :: "n"(N) : "memory");
}

__device__ __forceinline__ void ldmatrix_x4(uint32_t& r0, uint32_t& r1, uint32_t& r2, uint32_t& r3,
                                            uint32_t addr) {
    asm volatile("ldmatrix.sync.aligned.m8n8.x4.shared.b16 {%0,%1,%2,%3}, [%4];"
        : "=r"(r0), "=r"(r1), "=r"(r2), "=r"(r3) : "r"(addr));
}

__device__ __forceinline__ void mma_16816(float* c, const uint32_t* a, uint32_t b0, uint32_t b1) {
    asm volatile("mma.sync.aligned.m16n8k16.row.col.f32.bf16.bf16.f32 "
        "{%0,%1,%2,%3}, {%4,%5,%6,%7}, {%8,%9}, {%0,%1,%2,%3};"
        : "+f"(c[0]), "+f"(c[1]), "+f"(c[2]), "+f"(c[3])
        : "r"(a[0]), "r"(a[1]), "r"(a[2]), "r"(a[3]), "r"(b0), "r"(b1));
}

// ---------------- kernel 1: fp32 -> bf16 + targets ----------------
__global__ void convert_kernel(const float* __restrict__ x, const int* __restrict__ tgt) {
    int tid = blockIdx.x * blockDim.x + threadIdx.x;
    int nthreads = gridDim.x * blockDim.x;
    const float4* x4 = (const float4*)x;
    uint2* out = (uint2*)g_xb;
    const int n4 = NROWS * DDIM / 4;
    for (int i = tid; i < n4; i += nthreads) {
        float4 v = x4[i];
        __nv_bfloat162 lo = __float22bfloat162_rn(make_float2(v.x, v.y));
        __nv_bfloat162 hi = __float22bfloat162_rn(make_float2(v.z, v.w));
        uint2 o;
        o.x = *(uint32_t*)&lo;
        o.y = *(uint32_t*)&hi;
        out[i] = o;
    }
    if (tid < NROWS) g_tgt[tid] = tgt[tid];
}

// ---------------- kernel 2: 128 x (64*NF) tile GEMM + fused epilogue --------
// NF = n8-fragments per warp. NF=4 -> BN=256 (full tile), NF=2 -> BN=128 (half tile).
// Warp layout: 2 warps along M (64 rows), 8 along N (8*NF cols each).
template <int NF>
__global__ void __launch_bounds__(NTHREADS, 1)
gemm_loss_kernel(int t_base, int divisor, int part_base) {
    constexpr int BM = 128;
    constexpr int BN = 64 * NF;
    constexpr int NGROUPS = (NF + 1) / 2;          // x4 B-load groups of 16 cols
    constexpr int A_BYTES = BM * 128;              // 16 KB per stage
    constexpr int B_BYTES = BN * 128;              // 32/16 KB per stage
    constexpr int STAGE_BYTES = A_BYTES + B_BYTES;
    // B fill: threads-per-row and bytes-per-thread for a 128B-wide chunk
    constexpr int TPR  = NTHREADS / BN;            // 2 (NF=4) or 4 (NF=2)
    constexpr int BCW  = 128 / TPR;                // 64 or 32 bytes per thread
    constexpr int BNLD = BCW / 16;                 // 4 or 2 x 16B loads

    extern __shared__ char smem[];
    __shared__ int   s_tgtA[BM];
    __shared__ int   s_tgtB[BN];
    __shared__ float s_red[16];

    const uint32_t smem_base = smem_to_u32(smem);
    const int tid = threadIdx.x;
    const int wid = tid >> 5;
    const int lid = tid & 31;

    // work unit -> tile index + N-slice
    const int t   = t_base + blockIdx.x / divisor;
    const int sub = blockIdx.x % divisor;

    // t -> (bi, bjc): row-tile bi has (bi/2 + 1) col-tiles (256-col units)
    int k = t;
    int bi = 0;
    for (;;) {
        int nb = (bi >> 1) + 1;
        if (k < nb) break;
        k -= nb;
        bi++;
    }
    const int row0 = bi * BM;
    const int col0 = k * 256 + sub * BN;

    if (tid < BM) s_tgtA[tid] = g_tgt[row0 + tid];
    if (tid < BN) s_tgtB[tid] = g_tgt[col0 + tid];

    const int warp_m = (wid & 1) * 64;
    const int warp_n = (wid >> 1) * (8 * NF);

    // ---- cp.async fill assignments (512 threads) ----
    // A: thread t -> row t>>2 (0..127), quarter (t&3)*32: 2 x 16B
    const int arow = tid >> 2;
    const int aq   = (tid & 3) * 32;
    // B: thread t -> row t/TPR, column (t%TPR)*BCW: BNLD x 16B
    const int brow = tid / TPR;
    const int bcol = (tid % TPR) * BCW;
    const char* gArow = (const char*)g_xb + ((size_t)(row0 + arow)) * (DDIM * 2) + aq;
    const char* gBrow = (const char*)g_xb + ((size_t)(col0 + brow)) * (DDIM * 2) + bcol;

    auto fill = [&](int kc, int buf) {
        uint32_t sA = smem_base + buf * STAGE_BYTES;
        uint32_t sB = sA + A_BYTES;
        const char* ga = gArow + kc * 128;
        const char* gb = gBrow + kc * 128;
        #pragma unroll
        for (int j = 0; j < 2; j++) {
            uint32_t off = SW128((uint32_t)(arow * 128 + aq + j * 16));
            cp_async16(sA + off, ga + j * 16);
        }
        #pragma unroll
        for (int j = 0; j < BNLD; j++) {
            uint32_t off = SW128((uint32_t)(brow * 128 + bcol + j * 16));
            cp_async16(sB + off, gb + j * 16);
        }
    };

    // ---- accumulators: warp tile 64 x (8*NF) = 4 (m16) x NF (n8) fragments ----
    float c[4][NF][4];
    #pragma unroll
    for (int mi = 0; mi < 4; mi++)
        #pragma unroll
        for (int ni = 0; ni < NF; ni++)
            #pragma unroll
            for (int e = 0; e < 4; e++) c[mi][ni][e] = 0.0f;

    const int lrow  = lid & 15;
    const int lkoff = (lid >> 4) * 16;

    // prologue
    #pragma unroll
    for (int s = 0; s < STAGES - 1; s++) { fill(s, s); cp_commit(); }

    for (int kc = 0; kc < NKCHUNKS; kc++) {
        const int buf = kc % STAGES;
        cp_wait<STAGES - 2>();
        __syncthreads();

        const int kf = kc + STAGES - 1;
        if (kf < NKCHUNKS) fill(kf, kf % STAGES);
        cp_commit();

        const uint32_t sA = smem_base + buf * STAGE_BYTES;
        const uint32_t sB = sA + A_BYTES;

        #pragma unroll
        for (int ks = 0; ks < BK / 16; ks++) {
            const int kbyte = ks * 32 + lkoff;
            uint32_t a[4][4];
            #pragma unroll
            for (int mi = 0; mi < 4; mi++) {
                uint32_t off = SW128((uint32_t)((warp_m + mi * 16 + lrow) * 128 + kbyte));
                ldmatrix_x4(a[mi][0], a[mi][1], a[mi][2], a[mi][3], sA + off);
            }
            uint32_t b[NGROUPS][4];
            #pragma unroll
            for (int ng = 0; ng < NGROUPS; ng++) {
                uint32_t off = SW128((uint32_t)((warp_n + ng * 16 + lrow) * 128 + kbyte));
                ldmatrix_x4(b[ng][0], b[ng][1], b[ng][2], b[ng][3], sB + off);
            }
            #pragma unroll
            for (int mi = 0; mi < 4; mi++)
                #pragma unroll
                for (int ni = 0; ni < NF; ni++) {
                    const int ng = ni >> 1, s2 = ni & 1;
                    mma_16816(c[mi][ni], a[mi], b[ng][s2], b[ng][2 + s2]);
                }
        }
    }
    __syncthreads();

    // ---- fused epilogue: masked hinge sums, strict lower triangle (weight 2) ----
    float acc = 0.0f;
    #pragma unroll
    for (int mi = 0; mi < 4; mi++) {
        const int lr0 = warp_m + mi * 16 + (lid >> 2);
        const int gr0 = row0 + lr0;
        const int gr1 = gr0 + 8;
        const int tr0 = s_tgtA[lr0];
        const int tr1 = s_tgtA[lr0 + 8];
        #pragma unroll
        for (int ni = 0; ni < NF; ni++) {
            const int lc0 = warp_n + ni * 8 + 2 * (lid & 3);
            const int gc0 = col0 + lc0;
            const int gc1 = gc0 + 1;
            const int tc0 = s_tgtB[lc0];
            const int tc1 = s_tgtB[lc0 + 1];
            const float* f = c[mi][ni];
            if (gc0 < gr0) {
                if (tr0 == tc0) { if (f[0] < 1.0f) acc += 1.0f - f[0]; } else if (f[0] > MARGIN) acc += f[0];
            }
            if (gc1 < gr0) {
                if (tr0 == tc1) { if (f[1] < 1.0f) acc += 1.0f - f[1]; } else if (f[1] > MARGIN) acc += f[1];
            }
            if (gc0 < gr1) {
                if (tr1 == tc0) { if (f[2] < 1.0f) acc += 1.0f - f[2]; } else if (f[2] > MARGIN) acc += f[2];
            }
            if (gc1 < gr1) {
                if (tr1 == tc1) { if (f[3] < 1.0f) acc += 1.0f - f[3]; } else if (f[3] > MARGIN) acc += f[3];
            }
        }
    }
    #pragma unroll
    for (int o = 16; o; o >>= 1) acc += __shfl_xor_sync(0xFFFFFFFFu, acc, o);
    if (lid == 0) s_red[wid] = acc;
    __syncthreads();
    if (tid == 0) {
        float tot = 0.0f;
        #pragma unroll
        for (int w = 0; w < 16; w++) tot += s_red[w];
        g_partials[part_base + blockIdx.x] = 2.0f * tot;
    }
}

// ---------------- kernel 3: deterministic final reduction ----------------
__global__ void reduce_kernel(float* __restrict__ out) {
    __shared__ float s[256];
    float v = 0.0f;
    for (int i = threadIdx.x; i < NPARTS; i += 256) v += g_partials[i];
    s[threadIdx.x] = v;
    __syncthreads();
    for (int o = 128; o; o >>= 1) {
        if (threadIdx.x < o) s[threadIdx.x] += s[threadIdx.x + o];
        __syncthreads();
    }
    if (threadIdx.x == 0) out[0] = s[0] / (float)NROWS;
}

// ---------------- launch ----------------
extern "C" void kernel_launch(void* const* d_in, const int* in_sizes, int n_in,
                              void* d_out, int out_size) {
    const float* x   = (const float*)d_in[0];
    const int*   tgt = (const int*)d_in[1];
    float* out = (float*)d_out;

    constexpr int SMEM4 = STAGES * (128 * 128 + 256 * 128);   // 144 KB
    constexpr int SMEM2 = STAGES * (128 * 128 + 128 * 128);   //  96 KB
    cudaFuncSetAttribute(gemm_loss_kernel<4>, cudaFuncAttributeMaxDynamicSharedMemorySize, SMEM4);
    cudaFuncSetAttribute(gemm_loss_kernel<2>, cudaFuncAttributeMaxDynamicSharedMemorySize, SMEM2);

    convert_kernel<<<4096, 256>>>(x, tgt);
    gemm_loss_kernel<4><<<NT_FULL, NTHREADS, SMEM4>>>(0, 1, 0);                    // 7 exact waves
    gemm_loss_kernel<2><<<2 * NT_SPLIT, NTHREADS, SMEM2>>>(NT_FULL, 2, NT_FULL);   // 1 cheap wave
    reduce_kernel<<<1, 256>>>(out);
}

// round 13
// speedup vs baseline: 1.5654x; 1.5654x over previous
#include <cuda_runtime.h>
#include <cuda_bf16.h>
#include <cstdint>

// ---------------- problem constants ----------------
static constexpr int NROWS   = 8192;
static constexpr int DDIM    = 1024;
static constexpr float MARGIN = 0.3f;

// Tile enumeration in units of 128x256 tiles over the lower triangle:
// row-tile bi (of 64, 128 rows each) needs col-tiles 0..bi/2 -> 1056 total.
// First 1036 = 7 x 148 run as full tiles (7 exact waves);
// last 20 split into 40 half-tiles (128x128) in one cheap wave.
static constexpr int NT_FULL  = 1036;
static constexpr int NT_SPLIT = 20;
static constexpr int NPARTS   = NT_FULL + 2 * NT_SPLIT;   // 1076 partials

static constexpr int STAGES   = 3;
static constexpr int BK       = 64;                 // bf16 per K chunk (128 B/row)
static constexpr int NKCHUNKS = DDIM / BK;          // 16
static constexpr int NTHREADS = 512;                // 16 warps -> 4 per SMSP

// ---------------- scratch (no allocs allowed) ----------------
__device__ __nv_bfloat16 g_xb[(size_t)NROWS * DDIM];  // 16MB bf16 copy of X
__device__ int   g_tgt[NROWS];
__device__ float g_partials[NPARTS];

// ---------------- helpers ----------------
__device__ __forceinline__ uint32_t smem_to_u32(const void* p) {
    uint32_t a;
    asm("{ .reg .u64 t; cvta.to.shared.u64 t, %1; cvt.u32.u64 %0, t; }" : "=r"(a) : "l"(p));
    return a;
}
#define SW128(off) ((off) ^ (((off) >> 3) & 0x70))

__device__ __forceinline__ void cp_async16(uint32_t smem_dst, const void* gptr) {
    asm volatile("cp.async.cg.shared.global [%0], [%1], 16;"
        :: "r"(smem_dst), "l"(__cvta_generic_to_global(gptr)) : "memory");
}
__device__ __forceinline__ void cp_commit() {
    asm volatile("cp.async.commit_group;" ::: "memory");
}
template <int N> __device__ __forceinline__ void cp_wait() {
    asm volatile("cp.async.wait_group %0;" :: "n"(N) : "memory");
}

__device__ __forceinline__ void ldmatrix_x4(uint32_t& r0, uint32_t& r1, uint32_t& r2, uint32_t& r3,
                                            uint32_t addr) {
    asm volatile("ldmatrix.sync.aligned.m8n8.x4.shared.b16 {%0,%1,%2,%3}, [%4];"
        : "=r"(r0), "=r"(r1), "=r"(r2), "=r"(r3) : "r"(addr));
}

__device__ __forceinline__ void mma_16816(float* c, const uint32_t* a, uint32_t b0, uint32_t b1) {
    asm volatile("mma.sync.aligned.m16n8k16.row.col.f32.bf16.bf16.f32 "
        "{%0,%1,%2,%3}, {%4,%5,%6,%7}, {%8,%9}, {%0,%1,%2,%3};"
        : "+f"(c[0]), "+f"(c[1]), "+f"(c[2]), "+f"(c[3])
        : "r"(a[0]), "r"(a[1]), "r"(a[2]), "r"(a[3]), "r"(b0), "r"(b1));
}

// ---------------- kernel 1: fp32 -> bf16 + targets ----------------
__global__ void convert_kernel(const float* __restrict__ x, const int* __restrict__ tgt) {
    int tid = blockIdx.x * blockDim.x + threadIdx.x;
    int nthreads = gridDim.x * blockDim.x;
    const float4* x4 = (const float4*)x;
    uint2* out = (uint2*)g_xb;
    const int n4 = NROWS * DDIM / 4;
    for (int i = tid; i < n4; i += nthreads) {
        float4 v = x4[i];
        __nv_bfloat162 lo = __float22bfloat162_rn(make_float2(v.x, v.y));
        __nv_bfloat162 hi = __float22bfloat162_rn(make_float2(v.z, v.w));
        uint2 o;
        o.x = *(uint32_t*)&lo;
        o.y = *(uint32_t*)&hi;
        out[i] = o;
    }
    if (tid < NROWS) g_tgt[tid] = tgt[tid];
}

// ---------------- GEMM tile body (compile-time specialized, no runtime params) ----
// HALF=false: full 128x256 tile, t = blockIdx.x, sub = 0, partial slot = blockIdx.x.
// HALF=true:  128x128 half tile, t = NT_FULL + (blockIdx.x>>1), sub = blockIdx.x&1,
//             partial slot = NT_FULL + blockIdx.x.  All shifts, no division.
template <bool HALF>
__device__ __forceinline__ void gemm_body() {
    constexpr int NF = HALF ? 2 : 4;
    constexpr int BM = 128;
    constexpr int BN = 64 * NF;
    constexpr int NGROUPS = NF / 2 ? (NF + 1) / 2 : 1;   // 2 (full) / 1 (half)
    constexpr int A_BYTES = BM * 128;
    constexpr int B_BYTES = BN * 128;
    constexpr int STAGE_BYTES = A_BYTES + B_BYTES;
    constexpr int TPR  = NTHREADS / BN;                  // 2 / 4
    constexpr int BCW  = 128 / TPR;                      // 64 / 32
    constexpr int BNLD = BCW / 16;                       // 4 / 2

    extern __shared__ char smem[];
    __shared__ int   s_tgtA[BM];
    __shared__ int   s_tgtB[BN];
    __shared__ float s_red[16];

    const uint32_t smem_base = smem_to_u32(smem);
    const int tid = threadIdx.x;
    const int wid = tid >> 5;
    const int lid = tid & 31;

    const int t   = HALF ? (NT_FULL + (int)(blockIdx.x >> 1)) : (int)blockIdx.x;
    const int sub = HALF ? (int)(blockIdx.x & 1) : 0;

    // t -> (bi, k): row-tile bi has (bi/2 + 1) col-tiles (256-col units)
    int k = t;
    int bi = 0;
    for (;;) {
        int nb = (bi >> 1) + 1;
        if (k < nb) break;
        k -= nb;
        bi++;
    }
    const int row0 = bi * BM;
    const int col0 = k * 256 + sub * BN;

    if (tid < BM) s_tgtA[tid] = g_tgt[row0 + tid];
    if (tid < BN) s_tgtB[tid] = g_tgt[col0 + tid];

    const int warp_m = (wid & 1) * 64;
    const int warp_n = (wid >> 1) * (8 * NF);

    // A: thread t -> row t>>2, quarter (t&3)*32: 2 x 16B
    const int arow = tid >> 2;
    const int aq   = (tid & 3) * 32;
    // B: thread t -> row t/TPR, column (t%TPR)*BCW: BNLD x 16B  (TPR is 2 or 4 -> shifts)
    const int brow = tid / TPR;
    const int bcol = (tid % TPR) * BCW;
    const char* gArow = (const char*)g_xb + ((size_t)(row0 + arow)) * (DDIM * 2) + aq;
    const char* gBrow = (const char*)g_xb + ((size_t)(col0 + brow)) * (DDIM * 2) + bcol;

    auto fill = [&](int kc, int buf) {
        uint32_t sA = smem_base + buf * STAGE_BYTES;
        uint32_t sB = sA + A_BYTES;
        const char* ga = gArow + kc * 128;
        const char* gb = gBrow + kc * 128;
        #pragma unroll
        for (int j = 0; j < 2; j++) {
            uint32_t off = SW128((uint32_t)(arow * 128 + aq + j * 16));
            cp_async16(sA + off, ga + j * 16);
        }
        #pragma unroll
        for (int j = 0; j < BNLD; j++) {
            uint32_t off = SW128((uint32_t)(brow * 128 + bcol + j * 16));
            cp_async16(sB + off, gb + j * 16);
        }
    };

    float c[4][NF][4];
    #pragma unroll
    for (int mi = 0; mi < 4; mi++)
        #pragma unroll
        for (int ni = 0; ni < NF; ni++)
            #pragma unroll
            for (int e = 0; e < 4; e++) c[mi][ni][e] = 0.0f;

    const int lrow  = lid & 15;
    const int lkoff = (lid >> 4) * 16;

    #pragma unroll
    for (int s = 0; s < STAGES - 1; s++) { fill(s, s); cp_commit(); }

    for (int kc = 0; kc < NKCHUNKS; kc++) {
        const int buf = kc % STAGES;
        cp_wait<STAGES - 2>();
        __syncthreads();

        const int kf = kc + STAGES - 1;
        if (kf < NKCHUNKS) fill(kf, kf % STAGES);
        cp_commit();

        const uint32_t sA = smem_base + buf * STAGE_BYTES;
        const uint32_t sB = sA + A_BYTES;

        #pragma unroll
        for (int ks = 0; ks < BK / 16; ks++) {
            const int kbyte = ks * 32 + lkoff;
            uint32_t a[4][4];
            #pragma unroll
            for (int mi = 0; mi < 4; mi++) {
                uint32_t off = SW128((uint32_t)((warp_m + mi * 16 + lrow) * 128 + kbyte));
                ldmatrix_x4(a[mi][0], a[mi][1], a[mi][2], a[mi][3], sA + off);
            }
            uint32_t b[NGROUPS][4];
            #pragma unroll
            for (int ng = 0; ng < NGROUPS; ng++) {
                uint32_t off = SW128((uint32_t)((warp_n + ng * 16 + lrow) * 128 + kbyte));
                ldmatrix_x4(b[ng][0], b[ng][1], b[ng][2], b[ng][3], sB + off);
            }
            #pragma unroll
            for (int mi = 0; mi < 4; mi++)
                #pragma unroll
                for (int ni = 0; ni < NF; ni++) {
                    const int ng = ni >> 1, s2 = ni & 1;
                    mma_16816(c[mi][ni], a[mi], b[ng][s2], b[ng][2 + s2]);
                }
        }
    }
    __syncthreads();

    // ---- fused epilogue: masked hinge sums, strict lower triangle (weight 2) ----
    float acc = 0.0f;
    #pragma unroll
    for (int mi = 0; mi < 4; mi++) {
        const int lr0 = warp_m + mi * 16 + (lid >> 2);
        const int gr0 = row0 + lr0;
        const int gr1 = gr0 + 8;
        const int tr0 = s_tgtA[lr0];
        const int tr1 = s_tgtA[lr0 + 8];
        #pragma unroll
        for (int ni = 0; ni < NF; ni++) {
            const int lc0 = warp_n + ni * 8 + 2 * (lid & 3);
            const int gc0 = col0 + lc0;
            const int gc1 = gc0 + 1;
            const int tc0 = s_tgtB[lc0];
            const int tc1 = s_tgtB[lc0 + 1];
            const float* f = c[mi][ni];
            if (gc0 < gr0) {
                if (tr0 == tc0) { if (f[0] < 1.0f) acc += 1.0f - f[0]; } else if (f[0] > MARGIN) acc += f[0];
            }
            if (gc1 < gr0) {
                if (tr0 == tc1) { if (f[1] < 1.0f) acc += 1.0f - f[1]; } else if (f[1] > MARGIN) acc += f[1];
            }
            if (gc0 < gr1) {
                if (tr1 == tc0) { if (f[2] < 1.0f) acc += 1.0f - f[2]; } else if (f[2] > MARGIN) acc += f[2];
            }
            if (gc1 < gr1) {
                if (tr1 == tc1) { if (f[3] < 1.0f) acc += 1.0f - f[3]; } else if (f[3] > MARGIN) acc += f[3];
            }
        }
    }
    #pragma unroll
    for (int o = 16; o; o >>= 1) acc += __shfl_xor_sync(0xFFFFFFFFu, acc, o);
    if (lid == 0) s_red[wid] = acc;
    __syncthreads();
    if (tid == 0) {
        float tot = 0.0f;
        #pragma unroll
        for (int w = 0; w < 16; w++) tot += s_red[w];
        const int slot = HALF ? (NT_FULL + (int)blockIdx.x) : (int)blockIdx.x;
        g_partials[slot] = 2.0f * tot;
    }
}

__global__ void __launch_bounds__(NTHREADS, 1) gemm_full_kernel() { gemm_body<false>(); }
__global__ void __launch_bounds__(NTHREADS, 1) gemm_half_kernel() { gemm_body<true>(); }

// ---------------- kernel 3: deterministic final reduction ----------------
__global__ void reduce_kernel(float* __restrict__ out) {
    __shared__ float s[256];
    float v = 0.0f;
    for (int i = threadIdx.x; i < NPARTS; i += 256) v += g_partials[i];
    s[threadIdx.x] = v;
    __syncthreads();
    for (int o = 128; o; o >>= 1) {
        if (threadIdx.x < o) s[threadIdx.x] += s[threadIdx.x + o];
        __syncthreads();
    }
    if (threadIdx.x == 0) out[0] = s[0] / (float)NROWS;
}

// ---------------- launch ----------------
extern "C" void kernel_launch(void* const* d_in, const int* in_sizes, int n_in,
                              void* d_out, int out_size) {
    const float* x   = (const float*)d_in[0];
    const int*   tgt = (const int*)d_in[1];
    float* out = (float*)d_out;

    constexpr int SMEM_FULL = STAGES * (128 * 128 + 256 * 128);   // 144 KB
    constexpr int SMEM_HALF = STAGES * (128 * 128 + 128 * 128);   //  96 KB
    cudaFuncSetAttribute(gemm_full_kernel, cudaFuncAttributeMaxDynamicSharedMemorySize, SMEM_FULL);
    cudaFuncSetAttribute(gemm_half_kernel, cudaFuncAttributeMaxDynamicSharedMemorySize, SMEM_HALF);

    convert_kernel<<<4096, 256>>>(x, tgt);
    gemm_full_kernel<<<NT_FULL, NTHREADS, SMEM_FULL>>>();        // 7 exact waves
    gemm_half_kernel<<<2 * NT_SPLIT, NTHREADS, SMEM_HALF>>>();   // 1 cheap wave
    reduce_kernel<<<1, 256>>>(out);
}